// round 9
// baseline (speedup 1.0000x reference)
#include <cuda_runtime.h>

#define FULL 0xffffffffu

typedef unsigned long long u64;

struct C { float x, y; };

// ---------- f32x2 packed helpers ----------
__device__ __forceinline__ u64 PK(float lo, float hi) {
    u64 r;
    asm("mov.b64 %0, {%1, %2};" : "=l"(r)
        : "r"(__float_as_uint(lo)), "r"(__float_as_uint(hi)));
    return r;
}
__device__ __forceinline__ void UPK(u64 p, float& lo, float& hi) {
    unsigned a, b;
    asm("mov.b64 {%0, %1}, %2;" : "=r"(a), "=r"(b) : "l"(p));
    lo = __uint_as_float(a); hi = __uint_as_float(b);
}
__device__ __forceinline__ u64 F2(u64 a, u64 b, u64 c) {
    u64 d;
    asm("fma.rn.f32x2 %0, %1, %2, %3;" : "=l"(d) : "l"(a), "l"(b), "l"(c));
    return d;
}
__device__ __forceinline__ u64 M2(u64 a, u64 b) {
    u64 d;
    asm("mul.rn.f32x2 %0, %1, %2;" : "=l"(d) : "l"(a), "l"(b));
    return d;
}
__device__ __forceinline__ u64 B2(float v) { return PK(v, v); }
__device__ __forceinline__ u64 SW64(u64 p) { float l, h; UPK(p, l, h); return PK(h, l); }
__device__ __forceinline__ u64 SHX64(u64 p, int m) {
    float l, h; UPK(p, l, h);
    return PK(__shfl_xor_sync(FULL, l, m), __shfl_xor_sync(FULL, h, m));
}
__device__ __forceinline__ C cmul(C a, C b) {
    C r;
    r.x = fmaf(a.x, b.x, -a.y * b.y);
    r.y = fmaf(a.x, b.y,  a.y * b.x);
    return r;
}
__device__ __forceinline__ void cmulp(u64& X, u64& Y, C c) {
    u64 cx = B2(c.x), cy = B2(c.y), ny = B2(-c.y);
    u64 nX = F2(cx, X, M2(ny, Y));
    u64 nY = F2(cx, Y, M2(cy, X));
    X = nX; Y = nY;
}

// ---------- precomputed Rot matrices (weight-only, grid-uniform) ----------
__device__ float4 g_U[60];  // SU(2) Rot -> {a.x,a.y,b.x,b.y}

__global__ void prep_kernel(const float* __restrict__ weights) {
    int idx = threadIdx.x;
    if (idx >= 60) return;
    float phi = weights[3 * idx + 0];
    float th  = weights[3 * idx + 1];
    float om  = weights[3 * idx + 2];
    float st, ct, sa, ca, sb, cb;
    __sincosf(0.5f * th,         &st, &ct);
    __sincosf(0.5f * (phi + om), &sa, &ca);
    __sincosf(0.5f * (phi - om), &sb, &cb);
    g_U[idx] = make_float4(ca * ct, -sa * ct, -cb * st, -sb * st);
}

// Packed swizzles of ag / bg for vectorized buildG (precomputed once per thread).
struct GPacks {
    u64 agP, agN, agC, agR;        // {ag.x,ag.y} {-ag.y,ag.x} {ag.x,-ag.y} {ag.y,ag.x}
    u64 bgA_e, bgB_e, bgP_e, bgN_e;
    u64 bgA_o, bgB_o, bgP_o, bgN_o;
};

// Vectorized fused-gate build: returns packed {ga.x,ga.y} and {gb.x,gb.y}.
__device__ __forceinline__ void buildG2(float4 u, const GPacks& P, bool odd,
                                        u64& gaP, u64& gbP) {
    const u64 ax = B2(u.x), ay = B2(u.y), bx = B2(u.z), by = B2(u.w);
    const u64 bgA = odd ? P.bgA_o : P.bgA_e;
    const u64 bgB = odd ? P.bgB_o : P.bgB_e;
    const u64 bgP = odd ? P.bgP_o : P.bgP_e;
    const u64 bgN = odd ? P.bgN_o : P.bgN_e;
    gaP = F2(ax, P.agP, F2(ay, P.agN, F2(bx, bgA, M2(by, bgB))));
    gbP = F2(ax, bgP, F2(ay, bgN, F2(bx, P.agC, M2(by, P.agR))));
}

// ---------- CNOT ring on packed state ----------
__device__ __forceinline__ void ring(u64 (&X)[16], u64 (&Y)[16],
                                     int srcLo, int srcHi, bool c0) {
#pragma unroll
    for (int k = 0; k < 16; k++)
        if ((k & 8) && !(k & 4)) { u64 t = X[k]; X[k] = X[k ^ 4]; X[k ^ 4] = t;
                                   t = Y[k]; Y[k] = Y[k ^ 4]; Y[k ^ 4] = t; }
#pragma unroll
    for (int k = 0; k < 16; k++)
        if ((k & 4) && !(k & 2)) { u64 t = X[k]; X[k] = X[k ^ 2]; X[k ^ 2] = t;
                                   t = Y[k]; Y[k] = Y[k ^ 2]; Y[k ^ 2] = t; }
#pragma unroll
    for (int k = 0; k < 16; k++)
        if ((k & 2) && !(k & 1)) { u64 t = X[k]; X[k] = X[k ^ 1]; X[k ^ 1] = t;
                                   t = Y[k]; Y[k] = Y[k ^ 1]; Y[k ^ 1] = t; }
#pragma unroll
    for (int k = 0; k < 16; k++) {
        float xl, xh, yl, yh;
        UPK(X[k], xl, xh); UPK(Y[k], yl, yh);
        float nxl, nxh, nyl, nyh;
        if (k & 1) {
            nxl = __shfl_sync(FULL, xh, srcLo); nxh = __shfl_sync(FULL, xl, srcHi);
            nyl = __shfl_sync(FULL, yh, srcLo); nyh = __shfl_sync(FULL, yl, srcHi);
        } else {
            nxl = __shfl_sync(FULL, xl, srcLo); nxh = __shfl_sync(FULL, xh, srcHi);
            nyl = __shfl_sync(FULL, yl, srcLo); nyh = __shfl_sync(FULL, yh, srcHi);
        }
        X[k] = PK(nxl, nxh); Y[k] = PK(nyl, nyh);
    }
#pragma unroll
    for (int k = 0; k < 8; k++) {
        u64 a = X[k], d = X[k + 8];
        X[k] = c0 ? d : a; X[k + 8] = c0 ? a : d;
        a = Y[k]; d = Y[k + 8];
        Y[k] = c0 ? d : a; Y[k + 8] = c0 ? a : d;
    }
}

// ===================== main kernel =====================
__global__ void __launch_bounds__(256, 2)
qsim_kernel(const float* __restrict__ x,
            const float* __restrict__ post_W,
            const float* __restrict__ post_b,
            const float* __restrict__ readout,
            const float* __restrict__ bias,
            float* __restrict__ out,
            int batch)
{
    const int lane = threadIdx.x & 31;
    const int samp = (int)((blockIdx.x * blockDim.x + threadIdx.x) >> 5);
    if (samp >= batch) return;

    const float x0 = x[2 * samp + 0];
    const float x1 = x[2 * samp + 1];
    float sx0, cx0, sx1, cx1;
    __sincosf(0.5f * x0, &sx0, &cx0);
    __sincosf(0.5f * x1, &sx1, &cx1);

    const C ag   { cx1 * cx0,  sx1 * sx0 };
    const C bg_e { -sx1 * cx0, -cx1 * sx0 };
    const C bg_o { -sx0 * cx1, -cx0 * sx1 };

    GPacks P;
    P.agP = PK(ag.x, ag.y);   P.agN = PK(-ag.y, ag.x);
    P.agC = PK(ag.x, -ag.y);  P.agR = PK(ag.y, ag.x);
    P.bgA_e = PK(-bg_e.x, bg_e.y); P.bgB_e = PK(-bg_e.y, -bg_e.x);
    P.bgP_e = PK(bg_e.x, bg_e.y);  P.bgN_e = PK(-bg_e.y, bg_e.x);
    P.bgA_o = PK(-bg_o.x, bg_o.y); P.bgB_o = PK(-bg_o.y, -bg_o.x);
    P.bgP_o = PK(bg_o.x, bg_o.y);  P.bgN_o = PK(-bg_o.y, bg_o.x);

    int gsrc = lane;
    gsrc = (gsrc & 2)  ? (gsrc ^ 1) : gsrc;
    gsrc = (gsrc & 4)  ? (gsrc ^ 2) : gsrc;
    gsrc = (gsrc & 8)  ? (gsrc ^ 4) : gsrc;
    gsrc = (gsrc & 16) ? (gsrc ^ 8) : gsrc;
    const int srcLo = gsrc, srcHi = gsrc ^ 16;
    const bool c0 = (lane & 1) != 0;

    u64 X[16], Y[16];

    // ======== layer 0: product state built directly ========
    {
        C f0[10], f1[10];
#pragma unroll
        for (int w = 0; w < 10; w++) {
            u64 gaP, gbP;
            buildG2(g_U[w], P, (w & 1) != 0, gaP, gbP);
            float gax, gay, gbx, gby;
            UPK(gaP, gax, gay); UPK(gbP, gbx, gby);
            f0[w] = C{gax, gay};
            f1[w] = C{-gbx, gby};
        }
        C Lc = ((lane >> 4) & 1) ? f1[5] : f0[5];
        Lc = cmul(Lc, ((lane >> 3) & 1) ? f1[6] : f0[6]);
        Lc = cmul(Lc, ((lane >> 2) & 1) ? f1[7] : f0[7]);
        Lc = cmul(Lc, ((lane >> 1) & 1) ? f1[8] : f0[8]);
        Lc = cmul(Lc, ( lane       & 1) ? f1[9] : f0[9]);
        C h0 = cmul(Lc, f0[4]);
        C h1 = cmul(Lc, f1[4]);
        X[0] = PK(h0.x, h1.x);
        Y[0] = PK(h0.y, h1.y);
        X[1] = X[0]; Y[1] = Y[0];
        cmulp(X[0], Y[0], f0[3]); cmulp(X[1], Y[1], f1[3]);
#pragma unroll
        for (int k = 0; k < 2; k++) {
            X[k + 2] = X[k]; Y[k + 2] = Y[k];
            cmulp(X[k], Y[k], f0[2]); cmulp(X[k + 2], Y[k + 2], f1[2]);
        }
#pragma unroll
        for (int k = 0; k < 4; k++) {
            X[k + 4] = X[k]; Y[k + 4] = Y[k];
            cmulp(X[k], Y[k], f0[1]); cmulp(X[k + 4], Y[k + 4], f1[1]);
        }
#pragma unroll
        for (int k = 0; k < 8; k++) {
            X[k + 8] = X[k]; Y[k + 8] = Y[k];
            cmulp(X[k], Y[k], f0[0]); cmulp(X[k + 8], Y[k + 8], f1[0]);
        }
    }
    ring(X, Y, srcLo, srcHi, c0);

    // ======== layers 1..5 ========
#pragma unroll 1
    for (int layer = 1; layer < 6; layer++) {
        const float4* Ul = g_U + layer * 10;

#pragma unroll
        for (int w = 0; w < 10; w++) {
            u64 gaP, gbP;
            buildG2(Ul[w], P, (w & 1) != 0, gaP, gbP);
            float gax, gay, gbx, gby;
            UPK(gaP, gax, gay); UPK(gbP, gbx, gby);

            if (w <= 3) {
                const int ks = 8 >> w;
                const u64 paxx = B2(gax), pnay = B2(-gay), ppay = B2(gay);
                const u64 pbxx = B2(gbx), pnbx = B2(-gbx);
                const u64 pnby = B2(-gby), ppby = B2(gby);
#pragma unroll
                for (int kl = 0; kl < 16; kl++) {
                    if (kl & ks) continue;
                    const int kh = kl | ks;
                    u64 Xl = X[kl], Yl = Y[kl], Xh = X[kh], Yh = Y[kh];
                    X[kl] = F2(paxx, Xl, F2(pnay, Yl, F2(pbxx, Xh, M2(pnby, Yh))));
                    Y[kl] = F2(paxx, Yl, F2(ppay, Xl, F2(pbxx, Yh, M2(ppby, Xh))));
                    X[kh] = F2(paxx, Xh, F2(ppay, Yh, F2(pnbx, Xl, M2(pnby, Yl))));
                    Y[kh] = F2(paxx, Yh, F2(pnay, Xh, F2(pnbx, Yl, M2(ppby, Xl))));
                }
            } else if (w == 4) {
                const u64 qaxx = B2(gax);
                const u64 qay  = PK(-gay,  gay);
                const u64 qay2 = PK( gay, -gay);
                const u64 qbx  = PK( gbx, -gbx);
                const u64 qnby = B2(-gby), qpby = B2(gby);
#pragma unroll
                for (int k = 0; k < 16; k++) {
                    // own-part first, swap-dependent last
                    u64 ownX = F2(qaxx, X[k], M2(qay,  Y[k]));
                    u64 ownY = F2(qaxx, Y[k], M2(qay2, X[k]));
                    u64 Xs = SW64(X[k]), Ys = SW64(Y[k]);
                    u64 nX = F2(qbx, Xs, F2(qnby, Ys, ownX));
                    u64 nY = F2(qbx, Ys, F2(qpby, Xs, ownY));
                    X[k] = nX; Y[k] = nY;
                }
            } else {
                const int m = 1 << (9 - w);
                const bool hib = (lane & m) != 0;
                const float aly = hib ? -gay : gay;
                const float bex = hib ? -gbx : gbx;
                const u64 pA   = B2(gax);
                const u64 pAy  = B2(aly),  pnAy = B2(-aly);
                const u64 pBx  = B2(bex);
                const u64 pBy  = B2(gby), pnBy = B2(-gby);
#pragma unroll
                for (int k = 0; k < 16; k++) {
                    // compute shuffle-independent half first; cross terms last
                    u64 ownX = F2(pA, X[k], M2(pnAy, Y[k]));
                    u64 ownY = F2(pA, Y[k], M2(pAy,  X[k]));
                    u64 OX = SHX64(X[k], m), OY = SHX64(Y[k], m);
                    u64 nX = F2(pBx, OX, F2(pnBy, OY, ownX));
                    u64 nY = F2(pBx, OY, F2(pBy,  OX, ownY));
                    X[k] = nX; Y[k] = nY;
                }
            }
        }

        ring(X, Y, srcLo, srcHi, c0);
    }

    // ---- readout ----
    float pw[10];
#pragma unroll
    for (int w = 0; w < 10; w++) pw[w] = post_W[w];

    float laneCoef = 0.f;
#pragma unroll
    for (int w = 5; w < 10; w++)
        laneCoef += ((lane >> (9 - w)) & 1) ? -pw[w] : pw[w];

    u64 acc2 = 0ull;
#pragma unroll
    for (int k = 0; k < 16; k++) {
        float base = laneCoef;
#pragma unroll
        for (int w = 0; w < 4; w++)
            base += ((k >> (3 - w)) & 1) ? -pw[w] : pw[w];
        const u64 cp = PK(base + pw[4], base - pw[4]);
        const u64 p2 = F2(X[k], X[k], M2(Y[k], Y[k]));
        acc2 = F2(p2, cp, acc2);
    }
    float aLo, aHi;
    UPK(acc2, aLo, aHi);
    float acc = aLo + aHi;

#pragma unroll
    for (int off = 16; off; off >>= 1)
        acc += __shfl_xor_sync(FULL, acc, off);

    if (lane == 0)
        out[samp] = readout[0] * (acc + post_b[0]) + bias[0];
}

extern "C" void kernel_launch(void* const* d_in, const int* in_sizes, int n_in,
                              void* d_out, int out_size)
{
    const float* x       = (const float*)d_in[0];
    const float* weights = (const float*)d_in[1];
    const float* post_W  = (const float*)d_in[2];
    const float* post_b  = (const float*)d_in[3];
    const float* readout = (const float*)d_in[4];
    const float* bias    = (const float*)d_in[5];
    float* out = (float*)d_out;

    const int batch = in_sizes[0] / 2;
    prep_kernel<<<1, 64>>>(weights);

    const int threads = 256;
    const int total_threads = batch * 32;
    const int blocks = (total_threads + threads - 1) / threads;
    qsim_kernel<<<blocks, threads>>>(x, post_W, post_b, readout, bias, out, batch);
}

// round 11
// speedup vs baseline: 1.0681x; 1.0681x over previous
#include <cuda_runtime.h>

#define FULL 0xffffffffu

typedef unsigned long long u64;

struct C { float x, y; };

// ---------- f32x2 packed helpers ----------
__device__ __forceinline__ u64 PK(float lo, float hi) {
    u64 r;
    asm("mov.b64 %0, {%1, %2};" : "=l"(r)
        : "r"(__float_as_uint(lo)), "r"(__float_as_uint(hi)));
    return r;
}
__device__ __forceinline__ void UPK(u64 p, float& lo, float& hi) {
    unsigned a, b;
    asm("mov.b64 {%0, %1}, %2;" : "=r"(a), "=r"(b) : "l"(p));
    lo = __uint_as_float(a); hi = __uint_as_float(b);
}
__device__ __forceinline__ u64 F2(u64 a, u64 b, u64 c) {
    u64 d;
    asm("fma.rn.f32x2 %0, %1, %2, %3;" : "=l"(d) : "l"(a), "l"(b), "l"(c));
    return d;
}
__device__ __forceinline__ u64 M2(u64 a, u64 b) {
    u64 d;
    asm("mul.rn.f32x2 %0, %1, %2;" : "=l"(d) : "l"(a), "l"(b));
    return d;
}
__device__ __forceinline__ u64 B2(float v) { return PK(v, v); }
__device__ __forceinline__ u64 SW64(u64 p) { float l, h; UPK(p, l, h); return PK(h, l); }
__device__ __forceinline__ u64 SHX64(u64 p, int m) {
    float l, h; UPK(p, l, h);
    return PK(__shfl_xor_sync(FULL, l, m), __shfl_xor_sync(FULL, h, m));
}
__device__ __forceinline__ C cmul(C a, C b) {
    C r;
    r.x = fmaf(a.x, b.x, -a.y * b.y);
    r.y = fmaf(a.x, b.y,  a.y * b.x);
    return r;
}
__device__ __forceinline__ void cmulp(u64& X, u64& Y, C c) {
    u64 cx = B2(c.x), cy = B2(c.y), ny = B2(-c.y);
    u64 nX = F2(cx, X, M2(ny, Y));
    u64 nY = F2(cx, Y, M2(cy, X));
    X = nX; Y = nY;
}

// ---------- precomputed Rot matrices (weight-only, grid-uniform) ----------
__device__ float4 g_U[60];  // SU(2) Rot -> {a.x,a.y,b.x,b.y}

__global__ void prep_kernel(const float* __restrict__ weights) {
    int idx = threadIdx.x;
    if (idx >= 60) return;
    float phi = weights[3 * idx + 0];
    float th  = weights[3 * idx + 1];
    float om  = weights[3 * idx + 2];
    float st, ct, sa, ca, sb, cb;
    __sincosf(0.5f * th,         &st, &ct);
    __sincosf(0.5f * (phi + om), &sa, &ca);
    __sincosf(0.5f * (phi - om), &sb, &cb);
    g_U[idx] = make_float4(ca * ct, -sa * ct, -cb * st, -sb * st);
}

// fused gate coefficients: M = Rot * (RY*RX) in SU(2) form {ga, gb}  (scalar)
__device__ __forceinline__ void buildG(float4 u, C ag, C bg, C& ga, C& gb) {
    const C au{u.x, u.y}, bu{u.z, u.w};
    ga.x = fmaf(au.x, ag.x, fmaf(-au.y, ag.y, fmaf(-bu.x, bg.x, -bu.y * bg.y)));
    ga.y = fmaf(au.x, ag.y, fmaf( au.y, ag.x, fmaf(-bu.y, bg.x,  bu.x * bg.y)));
    gb.x = fmaf(au.x, bg.x, fmaf(-au.y, bg.y, fmaf( bu.x, ag.x,  bu.y * ag.y)));
    gb.y = fmaf(au.x, bg.y, fmaf( au.y, bg.x, fmaf( bu.y, ag.x, -bu.x * ag.y)));
}

// ---------- CNOT ring on packed state ----------
__device__ __forceinline__ void ring(u64 (&X)[16], u64 (&Y)[16],
                                     int srcLo, int srcHi, bool c0) {
#pragma unroll
    for (int k = 0; k < 16; k++)
        if ((k & 8) && !(k & 4)) { u64 t = X[k]; X[k] = X[k ^ 4]; X[k ^ 4] = t;
                                   t = Y[k]; Y[k] = Y[k ^ 4]; Y[k ^ 4] = t; }
#pragma unroll
    for (int k = 0; k < 16; k++)
        if ((k & 4) && !(k & 2)) { u64 t = X[k]; X[k] = X[k ^ 2]; X[k ^ 2] = t;
                                   t = Y[k]; Y[k] = Y[k ^ 2]; Y[k ^ 2] = t; }
#pragma unroll
    for (int k = 0; k < 16; k++)
        if ((k & 2) && !(k & 1)) { u64 t = X[k]; X[k] = X[k ^ 1]; X[k ^ 1] = t;
                                   t = Y[k]; Y[k] = Y[k ^ 1]; Y[k ^ 1] = t; }
#pragma unroll
    for (int k = 0; k < 16; k++) {
        float xl, xh, yl, yh;
        UPK(X[k], xl, xh); UPK(Y[k], yl, yh);
        float nxl, nxh, nyl, nyh;
        if (k & 1) {
            nxl = __shfl_sync(FULL, xh, srcLo); nxh = __shfl_sync(FULL, xl, srcHi);
            nyl = __shfl_sync(FULL, yh, srcLo); nyh = __shfl_sync(FULL, yl, srcHi);
        } else {
            nxl = __shfl_sync(FULL, xl, srcLo); nxh = __shfl_sync(FULL, xh, srcHi);
            nyl = __shfl_sync(FULL, yl, srcLo); nyh = __shfl_sync(FULL, yh, srcHi);
        }
        X[k] = PK(nxl, nxh); Y[k] = PK(nyl, nyh);
    }
#pragma unroll
    for (int k = 0; k < 8; k++) {
        u64 a = X[k], d = X[k + 8];
        X[k] = c0 ? d : a; X[k + 8] = c0 ? a : d;
        a = Y[k]; d = Y[k + 8];
        Y[k] = c0 ? d : a; Y[k + 8] = c0 ? a : d;
    }
}

// ===================== main kernel =====================
// amplitude i = k*64 + h*32 + lane; X[k] packs {Re(h=0),Re(h=1)}, Y imag.
// wire w <-> bit 9-w: w0..w3 -> pack bits 3..0, w4 -> half h, w5..w9 -> lane bits 4..0.
__global__ void __launch_bounds__(256, 2)
qsim_kernel(const float* __restrict__ x,
            const float* __restrict__ post_W,
            const float* __restrict__ post_b,
            const float* __restrict__ readout,
            const float* __restrict__ bias,
            float* __restrict__ out,
            int batch)
{
    const int lane = threadIdx.x & 31;
    const int samp = (int)((blockIdx.x * blockDim.x + threadIdx.x) >> 5);
    if (samp >= batch) return;

    const float x0 = x[2 * samp + 0];
    const float x1 = x[2 * samp + 1];
    float sx0, cx0, sx1, cx1;
    __sincosf(0.5f * x0, &sx0, &cx0);
    __sincosf(0.5f * x1, &sx1, &cx1);

    const C ag   { cx1 * cx0,  sx1 * sx0 };
    const C bg_e { -sx1 * cx0, -cx1 * sx0 };  // even wires: RX(x0), RY(x1)
    const C bg_o { -sx0 * cx1, -cx0 * sx1 };  // odd  wires: RX(x1), RY(x0)

    int gsrc = lane;
    gsrc = (gsrc & 2)  ? (gsrc ^ 1) : gsrc;
    gsrc = (gsrc & 4)  ? (gsrc ^ 2) : gsrc;
    gsrc = (gsrc & 8)  ? (gsrc ^ 4) : gsrc;
    gsrc = (gsrc & 16) ? (gsrc ^ 8) : gsrc;
    const int srcLo = gsrc, srcHi = gsrc ^ 16;
    const bool c0 = (lane & 1) != 0;

    // Which gate this lane builds (layers 1..5); lanes >= 10 duplicate gate 9.
    const int myw = lane < 10 ? lane : 9;
    const C myBg = (myw & 1) ? bg_o : bg_e;

    u64 X[16], Y[16];

    // ======== layer 0: product state built directly (scalar builds) ========
    {
        C f0[10], f1[10];
#pragma unroll
        for (int w = 0; w < 10; w++) {
            C ga, gb;
            buildG(g_U[w], ag, (w & 1) ? bg_o : bg_e, ga, gb);
            f0[w] = ga;
            f1[w] = C{-gb.x, gb.y};
        }
        C Lc = ((lane >> 4) & 1) ? f1[5] : f0[5];
        Lc = cmul(Lc, ((lane >> 3) & 1) ? f1[6] : f0[6]);
        Lc = cmul(Lc, ((lane >> 2) & 1) ? f1[7] : f0[7]);
        Lc = cmul(Lc, ((lane >> 1) & 1) ? f1[8] : f0[8]);
        Lc = cmul(Lc, ( lane       & 1) ? f1[9] : f0[9]);
        C h0 = cmul(Lc, f0[4]);
        C h1 = cmul(Lc, f1[4]);
        X[0] = PK(h0.x, h1.x);
        Y[0] = PK(h0.y, h1.y);
        X[1] = X[0]; Y[1] = Y[0];
        cmulp(X[0], Y[0], f0[3]); cmulp(X[1], Y[1], f1[3]);
#pragma unroll
        for (int k = 0; k < 2; k++) {
            X[k + 2] = X[k]; Y[k + 2] = Y[k];
            cmulp(X[k], Y[k], f0[2]); cmulp(X[k + 2], Y[k + 2], f1[2]);
        }
#pragma unroll
        for (int k = 0; k < 4; k++) {
            X[k + 4] = X[k]; Y[k + 4] = Y[k];
            cmulp(X[k], Y[k], f0[1]); cmulp(X[k + 4], Y[k + 4], f1[1]);
        }
#pragma unroll
        for (int k = 0; k < 8; k++) {
            X[k + 8] = X[k]; Y[k + 8] = Y[k];
            cmulp(X[k], Y[k], f0[0]); cmulp(X[k + 8], Y[k + 8], f1[0]);
        }
    }
    ring(X, Y, srcLo, srcHi, c0);

    // ======== layers 1..5: distributed gate build + butterflies ========
#pragma unroll 1
    for (int layer = 1; layer < 6; layer++) {
        const float4* Ul = g_U + layer * 10;

        // Lane `myw` builds gate myw's coefficients once for the whole layer.
        C myga, mygb;
        buildG(Ul[myw], ag, myBg, myga, mygb);

#pragma unroll
        for (int w = 0; w < 10; w++) {
            // broadcast gate w's coefficients from lane w
            const float gax = __shfl_sync(FULL, myga.x, w);
            const float gay = __shfl_sync(FULL, myga.y, w);
            const float gbx = __shfl_sync(FULL, mygb.x, w);
            const float gby = __shfl_sync(FULL, mygb.y, w);

            if (w <= 3) {
                const int ks = 8 >> w;
                const u64 paxx = B2(gax), pnay = B2(-gay), ppay = B2(gay);
                const u64 pbxx = B2(gbx), pnbx = B2(-gbx);
                const u64 pnby = B2(-gby), ppby = B2(gby);
#pragma unroll
                for (int kl = 0; kl < 16; kl++) {
                    if (kl & ks) continue;
                    const int kh = kl | ks;
                    u64 Xl = X[kl], Yl = Y[kl], Xh = X[kh], Yh = Y[kh];
                    X[kl] = F2(paxx, Xl, F2(pnay, Yl, F2(pbxx, Xh, M2(pnby, Yh))));
                    Y[kl] = F2(paxx, Yl, F2(ppay, Xl, F2(pbxx, Yh, M2(ppby, Xh))));
                    X[kh] = F2(paxx, Xh, F2(ppay, Yh, F2(pnbx, Xl, M2(pnby, Yl))));
                    Y[kh] = F2(paxx, Yh, F2(pnay, Xh, F2(pnbx, Yl, M2(ppby, Xl))));
                }
            } else if (w == 4) {
                const u64 qaxx = B2(gax);
                const u64 qay  = PK(-gay,  gay);
                const u64 qay2 = PK( gay, -gay);
                const u64 qbx  = PK( gbx, -gbx);
                const u64 qnby = B2(-gby), qpby = B2(gby);
#pragma unroll
                for (int k = 0; k < 16; k++) {
                    u64 ownX = F2(qaxx, X[k], M2(qay,  Y[k]));
                    u64 ownY = F2(qaxx, Y[k], M2(qay2, X[k]));
                    u64 Xs = SW64(X[k]), Ys = SW64(Y[k]);
                    u64 nX = F2(qbx, Xs, F2(qnby, Ys, ownX));
                    u64 nY = F2(qbx, Ys, F2(qpby, Xs, ownY));
                    X[k] = nX; Y[k] = nY;
                }
            } else {
                const int m = 1 << (9 - w);
                const bool hib = (lane & m) != 0;
                const float aly = hib ? -gay : gay;
                const float bex = hib ? -gbx : gbx;
                const u64 pA   = B2(gax);
                const u64 pAy  = B2(aly),  pnAy = B2(-aly);
                const u64 pBx  = B2(bex);
                const u64 pBy  = B2(gby), pnBy = B2(-gby);
#pragma unroll
                for (int k = 0; k < 16; k++) {
                    u64 ownX = F2(pA, X[k], M2(pnAy, Y[k]));
                    u64 ownY = F2(pA, Y[k], M2(pAy,  X[k]));
                    u64 OX = SHX64(X[k], m), OY = SHX64(Y[k], m);
                    u64 nX = F2(pBx, OX, F2(pnBy, OY, ownX));
                    u64 nY = F2(pBx, OY, F2(pBy,  OX, ownY));
                    X[k] = nX; Y[k] = nY;
                }
            }
        }

        ring(X, Y, srcLo, srcHi, c0);
    }

    // ---- readout ----
    float pw[10];
#pragma unroll
    for (int w = 0; w < 10; w++) pw[w] = post_W[w];

    float laneCoef = 0.f;
#pragma unroll
    for (int w = 5; w < 10; w++)
        laneCoef += ((lane >> (9 - w)) & 1) ? -pw[w] : pw[w];

    u64 acc2 = 0ull;
#pragma unroll
    for (int k = 0; k < 16; k++) {
        float base = laneCoef;
#pragma unroll
        for (int w = 0; w < 4; w++)
            base += ((k >> (3 - w)) & 1) ? -pw[w] : pw[w];
        const u64 cp = PK(base + pw[4], base - pw[4]);
        const u64 p2 = F2(X[k], X[k], M2(Y[k], Y[k]));
        acc2 = F2(p2, cp, acc2);
    }
    float aLo, aHi;
    UPK(acc2, aLo, aHi);
    float acc = aLo + aHi;

#pragma unroll
    for (int off = 16; off; off >>= 1)
        acc += __shfl_xor_sync(FULL, acc, off);

    if (lane == 0)
        out[samp] = readout[0] * (acc + post_b[0]) + bias[0];
}

extern "C" void kernel_launch(void* const* d_in, const int* in_sizes, int n_in,
                              void* d_out, int out_size)
{
    const float* x       = (const float*)d_in[0];
    const float* weights = (const float*)d_in[1];
    const float* post_W  = (const float*)d_in[2];
    const float* post_b  = (const float*)d_in[3];
    const float* readout = (const float*)d_in[4];
    const float* bias    = (const float*)d_in[5];
    float* out = (float*)d_out;

    const int batch = in_sizes[0] / 2;
    prep_kernel<<<1, 64>>>(weights);

    const int threads = 256;
    const int total_threads = batch * 32;
    const int blocks = (total_threads + threads - 1) / threads;
    qsim_kernel<<<blocks, threads>>>(x, post_W, post_b, readout, bias, out, batch);
}